// round 8
// baseline (speedup 1.0000x reference)
#include <cuda_runtime.h>
#include <math.h>

#ifndef M_PI
#define M_PI 3.14159265358979323846
#endif

#define NBT 48
#define NC  64
#define NX  128
#define NY  128
#define NB  4
#define TIN 12
#define TOUT 4
#define UD  3
#define NDEPTH 4

typedef unsigned long long u64;

__device__ __forceinline__ u64 f2fma(u64 a, u64 b, u64 c) {
    u64 r; asm("fma.rn.f32x2 %0,%1,%2,%3;" : "=l"(r) : "l"(a), "l"(b), "l"(c)); return r;
}
__device__ __forceinline__ u64 f2sub(u64 a, u64 b) {
    u64 r; asm("sub.rn.f32x2 %0,%1,%2;" : "=l"(r) : "l"(a), "l"(b)); return r;
}
__device__ __forceinline__ u64 f2pack(float lo, float hi) {
    u64 r; asm("mov.b64 %0,{%1,%2};" : "=l"(r) : "f"(lo), "f"(hi)); return r;
}
__device__ __forceinline__ u64 f2dup(float v) { return f2pack(v, v); }
__device__ __forceinline__ float2 f2unpack(u64 a) {
    float2 r; asm("mov.b64 {%0,%1},%2;" : "=f"(r.x), "=f"(r.y) : "l"(a)); return r;
}
__device__ __forceinline__ u64 f2neg(u64 a) { return a ^ 0x8000000080000000ULL; }

// ---------------- scratch ---------------------------------------------------
__device__ float g_X [NBT*NC*NX*NY];
__device__ float g_Yf[NBT*NC*NX*32];
__device__ float g_Zr[NBT*NC*512];
__device__ float g_Zi[NBT*NC*512];
__device__ float g_Or[NBT*NC*512];
__device__ float g_Oi[NBT*NC*512];
__device__ float g_Xi[NBT*NC*NX*32];
__device__ float g_Wfy2[64*32*2];
__device__ float g_Wfx[128*32*2];
__device__ float g_Wix[32*128*2];
__device__ float g_Cy [16*128];
__device__ float g_Sy [16*128];

// ---------------- table init ------------------------------------------------
__global__ void init_tables_kernel() {
    int tid = blockIdx.x * blockDim.x + threadIdx.x;
    if (tid < 64*32) {
        int yp = tid >> 5, k = tid & 31;
        int kk = k & 15;
        for (int j = 0; j < 2; j++) {
            int y = 2*yp + j;
            double th = (2.0 * M_PI / 128.0) * (double)((kk * y) & 127);
            g_Wfy2[tid*2 + j] = (k < 16) ? (float)cos(th) : (float)(-sin(th));
        }
    }
    if (tid < 128*32) {
        int x = tid >> 5, m = tid & 31;
        int kx = (m < 16) ? m : (96 + m);
        double th = (2.0 * M_PI / 128.0) * (double)((kx * x) & 127);
        g_Wfx[2*tid]   = (float)cos(th);
        g_Wfx[2*tid+1] = (float)(-sin(th));
    }
    if (tid < 32*128) {
        int m = tid >> 7, x = tid & 127;
        int kx = (m < 16) ? m : (96 + m);
        double th = (2.0 * M_PI / 128.0) * (double)((kx * x) & 127);
        g_Wix[2*tid]   = (float)(cos(th) / 128.0);
        g_Wix[2*tid+1] = (float)(sin(th) / 128.0);
    }
    if (tid < 16*128) {
        int k = tid >> 7, y = tid & 127;
        if (k == 0) { g_Cy[tid] = 1.0f/128.0f; g_Sy[tid] = 0.0f; }
        else {
            double th = (2.0 * M_PI / 128.0) * (double)((k * y) & 127);
            g_Cy[tid] = (float)( 2.0 * cos(th) / 128.0);
            g_Sy[tid] = (float)(-2.0 * sin(th) / 128.0);
        }
    }
}

// ---------------- fused lift (3->64) + forward y-DFT -----------------------
// grid (128 x, 48 bt), 256 threads
__global__ __launch_bounds__(256) void lift_fwdy_kernel(
    const float* __restrict__ in, const float* __restrict__ Pw,
    const float* __restrict__ Pb)
{
    __shared__ float sL[8192];     // lifted (c,y) line
    __shared__ float sPw[192], sPb[64], sIn[384];
    int tid = threadIdx.x;
    int x = blockIdx.x, bt = blockIdx.y;

    if (tid < 192) sPw[tid] = Pw[tid];
    if (tid < 64)  sPb[tid] = Pb[tid];
    if (tid < 128) {
#pragma unroll
        for (int u = 0; u < 3; u++)
            sIn[u*128 + tid] = in[((size_t)bt*3 + u)*16384 + x*128 + tid];
    }
    __syncthreads();

    // lift + write g_X
    for (int i = tid; i < 8192; i += 256) {
        int c = i >> 7, y = i & 127;
        float v = sPb[c] + sPw[c*3]*sIn[y] + sPw[c*3+1]*sIn[128+y] + sPw[c*3+2]*sIn[256+y];
        sL[i] = v;
        g_X[(((size_t)bt*64 + c)*128 + x)*128 + y] = v;
    }
    __syncthreads();

    // y-DFT: warp = 8 c-rows, lane = k
    int warp = tid >> 5, lane = tid & 31;
    const u64* w2 = (const u64*)g_Wfy2;
    int ob = warp * 8;
    u64 acc[8];
#pragma unroll
    for (int r = 0; r < 8; r++) acc[r] = 0ULL;
#pragma unroll 4
    for (int yp = 0; yp < 64; yp++) {
        u64 w = __ldg(w2 + yp*32 + lane);
#pragma unroll
        for (int r = 0; r < 8; r++) {
            u64 v2 = *(const u64*)(sL + (ob + r)*128 + 2*yp);
            acc[r] = f2fma(v2, w, acc[r]);
        }
    }
#pragma unroll
    for (int r = 0; r < 8; r++) {
        float2 p = f2unpack(acc[r]);
        g_Yf[(((size_t)bt*64 + ob + r)*128 + x)*32 + lane] = p.x + p.y;
    }
}

// ---------------- forward DFT over x (R6 version) --------------------------
__global__ __launch_bounds__(128) void fwd_x_kernel() {
    __shared__ float sY0[4096], sY1[4096];
    int tid = threadIdx.x;
    const float* src = g_Yf + (size_t)blockIdx.x * 8192;
    for (int i = tid; i < 4096; i += 128) { sY0[i] = src[i]; sY1[i] = src[4096 + i]; }
    __syncthreads();
    int m   = tid >> 2;
    int ky0 = (tid & 3) * 4;
    const float2* wtab = (const float2*)g_Wfx;
    u64 rA[2][2], rB[2][2], ii[2][2];
#pragma unroll
    for (int f = 0; f < 2; f++)
#pragma unroll
        for (int p = 0; p < 2; p++) { rA[f][p] = 0ULL; rB[f][p] = 0ULL; ii[f][p] = 0ULL; }
#pragma unroll 2
    for (int x = 0; x < 128; x++) {
        float2 w = __ldg(wtab + x*32 + m);
        u64 wr2 = f2dup(w.x), wi2 = f2dup(w.y);
        u64 a00 = *(const u64*)(sY0 + x*32 + ky0);
        u64 b00 = *(const u64*)(sY0 + x*32 + 16 + ky0);
        u64 a01 = *(const u64*)(sY0 + x*32 + ky0 + 2);
        u64 b01 = *(const u64*)(sY0 + x*32 + 18 + ky0);
        u64 a10 = *(const u64*)(sY1 + x*32 + ky0);
        u64 b10 = *(const u64*)(sY1 + x*32 + 16 + ky0);
        u64 a11 = *(const u64*)(sY1 + x*32 + ky0 + 2);
        u64 b11 = *(const u64*)(sY1 + x*32 + 18 + ky0);
        rA[0][0] = f2fma(a00, wr2, rA[0][0]);  rB[0][0] = f2fma(b00, wi2, rB[0][0]);
        ii[0][0] = f2fma(a00, wi2, ii[0][0]);  ii[0][0] = f2fma(b00, wr2, ii[0][0]);
        rA[0][1] = f2fma(a01, wr2, rA[0][1]);  rB[0][1] = f2fma(b01, wi2, rB[0][1]);
        ii[0][1] = f2fma(a01, wi2, ii[0][1]);  ii[0][1] = f2fma(b01, wr2, ii[0][1]);
        rA[1][0] = f2fma(a10, wr2, rA[1][0]);  rB[1][0] = f2fma(b10, wi2, rB[1][0]);
        ii[1][0] = f2fma(a10, wi2, ii[1][0]);  ii[1][0] = f2fma(b10, wr2, ii[1][0]);
        rA[1][1] = f2fma(a11, wr2, rA[1][1]);  rB[1][1] = f2fma(b11, wi2, rB[1][1]);
        ii[1][1] = f2fma(a11, wi2, ii[1][1]);  ii[1][1] = f2fma(b11, wr2, ii[1][1]);
    }
#pragma unroll
    for (int f = 0; f < 2; f++) {
        size_t base = ((size_t)(blockIdx.x*2 + f))*512 + m*16 + ky0;
        *(u64*)(g_Zr + base)     = f2sub(rA[f][0], rB[f][0]);
        *(u64*)(g_Zr + base + 2) = f2sub(rA[f][1], rB[f][1]);
        *(u64*)(g_Zi + base)     = ii[f][0];
        *(u64*)(g_Zi + base + 2) = ii[f][1];
    }
}

// ---------------- mode mix v2: block per mode-pair, all bt -----------------
// grid 256, 256 threads, dyn smem 114688 B
// smem: sZr[c][bt] u64, sZi, sWr[c][o] u64, sWi
__global__ __launch_bounds__(256) void mode_mix_kernel(
    const float* __restrict__ w1r, const float* __restrict__ w1i,
    const float* __restrict__ w2r, const float* __restrict__ w2i)
{
    extern __shared__ u64 smm[];
    u64* sZr = smm;                 // 3072
    u64* sZi = smm + 3072;          // 3072
    u64* sWr = smm + 6144;          // 4096
    u64* sWi = smm + 10240;         // 4096

    int tid = threadIdx.x;
    int mp    = blockIdx.x;         // 0..255
    int mode0 = mp * 2;
    int half  = mode0 >> 8;
    int ml    = mode0 & 255;
    const float* Wr = half ? w2r : w1r;
    const float* Wi = half ? w2i : w1i;

    for (int i = tid; i < 3072; i += 256) {
        int c = i / 48, bt = i - c*48;
        size_t zb = ((size_t)bt*64 + c)*512 + mode0;
        sZr[i] = *(const u64*)(g_Zr + zb);
        sZi[i] = *(const u64*)(g_Zi + zb);
    }
    for (int i = tid; i < 4096; i += 256) {
        size_t wb = (size_t)i*256 + ml;   // i = c*64 + o
        sWr[i] = *(const u64*)(Wr + wb);
        sWi[i] = *(const u64*)(Wi + wb);
    }
    __syncthreads();

    int og  = tid & 15, btg = tid >> 4;   // 16 x 16
    int o0  = og * 4;
    int bt0 = btg * 3;
    u64 aR[3][4], aI[3][4];
#pragma unroll
    for (int t = 0; t < 3; t++)
#pragma unroll
        for (int j = 0; j < 4; j++) { aR[t][j] = 0ULL; aI[t][j] = 0ULL; }

#pragma unroll 2
    for (int c = 0; c < 64; c++) {
        u64 zr0 = sZr[c*48 + bt0],     zi0 = sZi[c*48 + bt0];
        u64 zr1 = sZr[c*48 + bt0 + 1], zi1 = sZi[c*48 + bt0 + 1];
        u64 zr2 = sZr[c*48 + bt0 + 2], zi2 = sZi[c*48 + bt0 + 2];
#pragma unroll
        for (int j = 0; j < 4; j++) {
            u64 wr2  = sWr[c*64 + o0 + j];
            u64 wi2  = sWi[c*64 + o0 + j];
            u64 wi2n = f2neg(wi2);
            aR[0][j] = f2fma(zr0, wr2,  aR[0][j]);
            aR[0][j] = f2fma(zi0, wi2n, aR[0][j]);
            aI[0][j] = f2fma(zr0, wi2,  aI[0][j]);
            aI[0][j] = f2fma(zi0, wr2,  aI[0][j]);
            aR[1][j] = f2fma(zr1, wr2,  aR[1][j]);
            aR[1][j] = f2fma(zi1, wi2n, aR[1][j]);
            aI[1][j] = f2fma(zr1, wi2,  aI[1][j]);
            aI[1][j] = f2fma(zi1, wr2,  aI[1][j]);
            aR[2][j] = f2fma(zr2, wr2,  aR[2][j]);
            aR[2][j] = f2fma(zi2, wi2n, aR[2][j]);
            aI[2][j] = f2fma(zr2, wi2,  aI[2][j]);
            aI[2][j] = f2fma(zi2, wr2,  aI[2][j]);
        }
    }
#pragma unroll
    for (int t = 0; t < 3; t++)
#pragma unroll
        for (int j = 0; j < 4; j++) {
            size_t ob = ((size_t)(bt0 + t)*64 + (o0 + j))*512 + mode0;
            *(u64*)(g_Or + ob) = aR[t][j];
            *(u64*)(g_Oi + ob) = aI[t][j];
        }
}

// ---------------- inverse DFT over x ---------------------------------------
__global__ __launch_bounds__(256) void inv_x_kernel() {
    __shared__ float sOr[512], sOi[512];
    int tid = threadIdx.x;
    const float* srcr = g_Or + (size_t)blockIdx.x * 512;
    const float* srci = g_Oi + (size_t)blockIdx.x * 512;
    for (int i = tid; i < 512; i += 256) { sOr[i] = srcr[i]; sOi[i] = srci[i]; }
    __syncthreads();
    int x  = tid >> 1;
    int kb = (tid & 1) * 8;
    u64 arA[4], arB[4], ai[4];
#pragma unroll
    for (int j = 0; j < 4; j++) { arA[j] = 0ULL; arB[j] = 0ULL; ai[j] = 0ULL; }
#pragma unroll 4
    for (int m = 0; m < 32; m++) {
        float2 w = *(const float2*)(g_Wix + (m*128 + x)*2);
        u64 wr2 = f2dup(w.x), wi2 = f2dup(w.y);
#pragma unroll
        for (int j = 0; j < 4; j++) {
            u64 pr = *(const u64*)(sOr + m*16 + kb + 2*j);
            u64 pi = *(const u64*)(sOi + m*16 + kb + 2*j);
            arA[j] = f2fma(pr, wr2, arA[j]);
            arB[j] = f2fma(pi, wi2, arB[j]);
            ai[j]  = f2fma(pr, wi2, ai[j]);
            ai[j]  = f2fma(pi, wr2, ai[j]);
        }
    }
    float* dst = g_Xi + ((size_t)blockIdx.x * 128 + x) * 32;
#pragma unroll
    for (int j = 0; j < 4; j++) {
        *(u64*)(dst + kb + 2*j)      = f2sub(arA[j], arB[j]);
        *(u64*)(dst + 16 + kb + 2*j) = ai[j];
    }
}

// ---------------- fused tail (R7, unchanged) -------------------------------
__global__ __launch_bounds__(256) void fused_tail_kernel(
    const float* __restrict__ gctxd,
    const float* __restrict__ llw,
    const float* __restrict__ llb,
    const float* __restrict__ lng, const float* __restrict__ lnb,
    int write_yf)
{
    extern __shared__ float sm[];
    float* sXV  = sm;
    u64*   sLLd = (u64*)(sm + 8192);
    float* sCtx = sm + 8192;
    u64*   sXid = (u64*)(sm + 16384);
    float* sCy  = sm + 20480;
    float* sSy  = sm + 22528;
    float* sPS  = sm + 24576;
    float* sPQ  = sm + 24832;
    float* sMu  = sm + 25088;
    float* sRs  = sm + 25216;
    float* sLNg = sm + 25344;
    float* sLNb = sm + 25408;
    float* sLLb = sm + 25472;

    int tid = threadIdx.x;
    int x   = blockIdx.x;
    int bt  = blockIdx.y;

    float cxf = x * 0.5f - 0.25f;
    int ix0 = (int)floorf(cxf);
    float wx1 = cxf - (float)ix0, wx0 = 1.0f - wx1;
    int cx0 = min(63, max(0, ix0));
    int cx1 = min(63, max(0, ix0 + 1));

    for (int i = tid; i < 8192; i += 256) {
        int c = i >> 7, y = i & 127;
        sXV[i] = g_X[(((size_t)bt*64 + c)*128 + x)*128 + y];
    }
    for (int i = tid; i < 4096; i += 256) sLLd[i] = f2dup(llw[i]);
    for (int i = tid; i < 2048; i += 256) {
        int o = i >> 5, k = i & 31;
        sXid[i] = f2dup(g_Xi[(((size_t)bt*64 + o)*128 + x)*32 + k]);
    }
    for (int i = tid; i < 2048; i += 256) { sCy[i] = g_Cy[i]; sSy[i] = g_Sy[i]; }
    if (tid < 64) { sLNg[tid] = lng[tid]; sLNb[tid] = lnb[tid]; sLLb[tid] = llb[tid]; }
    __syncthreads();

    int o0  = (tid >> 5) * 8;
    int tx4 = (tid & 31) * 4;
    u64 acc0[8], acc1[8];
#pragma unroll
    for (int oo = 0; oo < 8; oo++) { acc0[oo] = 0ULL; acc1[oo] = 0ULL; }

#pragma unroll 2
    for (int c = 0; c < 64; c++) {
        ulonglong2 xv = *(const ulonglong2*)(sXV + c*128 + tx4);
#pragma unroll
        for (int oo = 0; oo < 8; oo++) {
            u64 w2 = sLLd[(o0 + oo)*64 + c];
            acc0[oo] = f2fma(xv.x, w2, acc0[oo]);
            acc1[oo] = f2fma(xv.y, w2, acc1[oo]);
        }
    }
#pragma unroll
    for (int ky = 0; ky < 16; ky++) {
        ulonglong2 cy = *(const ulonglong2*)(sCy + ky*128 + tx4);
        ulonglong2 sy = *(const ulonglong2*)(sSy + ky*128 + tx4);
#pragma unroll
        for (int oo = 0; oo < 8; oo++) {
            u64 xr2 = sXid[(o0 + oo)*32 + ky];
            u64 xi2 = sXid[(o0 + oo)*32 + 16 + ky];
            acc0[oo] = f2fma(xr2, cy.x, acc0[oo]);
            acc0[oo] = f2fma(xi2, sy.x, acc0[oo]);
            acc1[oo] = f2fma(xr2, cy.y, acc1[oo]);
            acc1[oo] = f2fma(xi2, sy.y, acc1[oo]);
        }
    }
    __syncthreads();
#pragma unroll
    for (int oo = 0; oo < 8; oo++) {
        float b = sLLb[o0 + oo];
        float2 v0 = f2unpack(acc0[oo]);
        float2 v1 = f2unpack(acc1[oo]);
        *(float4*)(sXV + (o0 + oo)*128 + tx4) =
            make_float4(v0.x + b, v0.y + b, v1.x + b, v1.y + b);
    }
    for (int i = tid; i < 8192; i += 256) {
        int o = i >> 7, rest = i & 127;
        int j = rest >> 6, c = rest & 63;
        int cx = j ? cx1 : cx0;
        sCtx[i] = gctxd[((size_t)bt*64 + o)*4096 + cx*64 + c];
    }
    __syncthreads();

    {
        int yy = tid & 127, oh = tid >> 7;
        float s = 0.f, ss = 0.f;
        int ob = oh * 32;
        for (int o = ob; o < ob + 32; o++) {
            float v = sXV[o*128 + yy];
            s += v; ss += v*v;
        }
        sPS[tid] = s; sPQ[tid] = ss;
    }
    __syncthreads();
    if (tid < 128) {
        float s = sPS[tid] + sPS[128 + tid];
        float q = sPQ[tid] + sPQ[128 + tid];
        float mu = s * (1.0f/64.0f);
        float var = q * (1.0f/64.0f) - mu*mu;
        sMu[tid] = mu;
        sRs[tid] = rsqrtf(var + 1e-5f);
    }
    __syncthreads();

    int y = tid & 127;
    float cyf = y * 0.5f - 0.25f;
    int iy0 = (int)floorf(cyf);
    float wy1 = cyf - (float)iy0, wy0 = 1.0f - wy1;
    int cy0 = min(63, max(0, iy0));
    int cy1 = min(63, max(0, iy0 + 1));
    float mu = sMu[y], rs = sRs[y];

    for (int j = 0; j < 32; j++) {
        int idx = j * 256 + tid;
        int o = idx >> 7;
        float v = sXV[o*128 + y];
        v = (v - mu) * rs * sLNg[o] + sLNb[o];
        v = 0.5f * v * (1.0f + erff(v * 0.70710678118654752440f));
        const float* cr = sCtx + o*128;
        float g = wx0 * (wy0 * cr[cy0] + wy1 * cr[cy1])
                + wx1 * (wy0 * cr[64 + cy0] + wy1 * cr[64 + cy1]);
        float fin = v + g;
        g_X[(((size_t)bt*64 + o)*128 + x)*128 + y] = fin;
        sXV[o*128 + y] = fin;
    }

    if (write_yf) {
        __syncthreads();
        int warp = tid >> 5, lane = tid & 31;
        const u64* w2 = (const u64*)g_Wfy2;
        int ob = warp * 8;
        u64 acc[8];
#pragma unroll
        for (int r = 0; r < 8; r++) acc[r] = 0ULL;
#pragma unroll 4
        for (int yp = 0; yp < 64; yp++) {
            u64 w = __ldg(w2 + yp*32 + lane);
#pragma unroll
            for (int r = 0; r < 8; r++) {
                u64 v2 = *(const u64*)(sXV + (ob + r)*128 + 2*yp);
                acc[r] = f2fma(v2, w, acc[r]);
            }
        }
#pragma unroll
        for (int r = 0; r < 8; r++) {
            float2 p = f2unpack(acc[r]);
            g_Yf[(((size_t)bt*64 + ob + r)*128 + x)*32 + lane] = p.x + p.y;
        }
    }
}

// ---------------- temporal aggregation + projection ------------------------
__global__ __launch_bounds__(256) void head_kernel(
    const float* __restrict__ Wtw, const float* __restrict__ Wtb,
    const float* __restrict__ Qw,  const float* __restrict__ Qb,
    float* __restrict__ out)
{
    __shared__ float sWt[48], sWtb[4], sQ[192], sQb[3], sQS[3];
    int tid = threadIdx.x;
    if (tid < 48)  sWt[tid]  = Wtw[tid];
    if (tid < 4)   sWtb[tid] = Wtb[tid];
    if (tid < 192) sQ[tid]   = Qw[tid];
    if (tid < 3)   sQb[tid]  = Qb[tid];
    __syncthreads();
    if (tid < 3) {
        float s = 0.f;
        for (int c = 0; c < 64; c++) s += sQ[tid*64 + c];
        sQS[tid] = s;
    }
    __syncthreads();
    int idx = blockIdx.x * 256 + tid;
    int b = idx >> 14, xy = idx & 16383;
    float acc[TOUT][UD] = {};
    for (int c = 0; c < 64; c++) {
        float xv[TIN];
#pragma unroll
        for (int t = 0; t < TIN; t++)
            xv[t] = g_X[(((size_t)(b*TIN + t))*64 + c)*16384 + xy];
        float tt[TOUT];
#pragma unroll
        for (int o = 0; o < TOUT; o++) {
            float s = 0.f;
#pragma unroll
            for (int t = 0; t < TIN; t++) s += sWt[o*TIN + t] * xv[t];
            tt[o] = s;
        }
#pragma unroll
        for (int u = 0; u < UD; u++) {
            float q = sQ[u*64 + c];
#pragma unroll
            for (int o = 0; o < TOUT; o++) acc[o][u] += q * tt[o];
        }
    }
#pragma unroll
    for (int o = 0; o < TOUT; o++)
#pragma unroll
        for (int u = 0; u < UD; u++)
            out[(((size_t)b*TOUT + o)*UD + u)*16384 + xy] =
                acc[o][u] + sWtb[o]*sQS[u] + sQb[u];
}

// ---------------- launcher --------------------------------------------------
extern "C" void kernel_launch(void* const* d_in, const int* in_sizes, int n_in,
                              void* d_out, int out_size)
{
    const float* input = (const float*)d_in[0];
    const float* gctx  = (const float*)d_in[1];
    const float* P_w   = (const float*)d_in[2];
    const float* P_b   = (const float*)d_in[3];
    const float* Q_w   = (const float*)d_in[4];
    const float* Q_b   = (const float*)d_in[5];
    const float* Wt_w  = (const float*)d_in[6];
    const float* Wt_b  = (const float*)d_in[7];
    const float* w1r   = (const float*)d_in[8];
    const float* w1i   = (const float*)d_in[9];
    const float* w2r   = (const float*)d_in[10];
    const float* w2i   = (const float*)d_in[11];
    const float* ll_w  = (const float*)d_in[12];
    const float* ll_b  = (const float*)d_in[13];
    const float* ln_g  = (const float*)d_in[14];
    const float* ln_b  = (const float*)d_in[15];
    float* out = (float*)d_out;

    const int FUSED_SMEM = 25536 * 4;   // 102144 bytes
    const int MM_SMEM    = 14336 * 8;   // 114688 bytes
    cudaFuncSetAttribute(fused_tail_kernel,
                         cudaFuncAttributeMaxDynamicSharedMemorySize, FUSED_SMEM);
    cudaFuncSetAttribute(mode_mix_kernel,
                         cudaFuncAttributeMaxDynamicSharedMemorySize, MM_SMEM);

    init_tables_kernel<<<16, 256>>>();
    dim3 gl(128, NBT);
    lift_fwdy_kernel<<<gl, 256>>>(input, P_w, P_b);

    const size_t SPEC_D = (size_t)64*64*16*16;
    for (int d = 0; d < NDEPTH; d++) {
        fwd_x_kernel<<<1536, 128>>>();
        mode_mix_kernel<<<256, 256, MM_SMEM>>>(w1r + d*SPEC_D, w1i + d*SPEC_D,
                                               w2r + d*SPEC_D, w2i + d*SPEC_D);
        inv_x_kernel<<<NBT*NC, 256>>>();
        dim3 g5(128, NBT);
        fused_tail_kernel<<<g5, 256, FUSED_SMEM>>>(
            gctx + (size_t)d*NBT*64*4096,
            ll_w + (size_t)d*4096, ll_b + d*64, ln_g + d*64, ln_b + d*64,
            (d < NDEPTH-1) ? 1 : 0);
    }
    head_kernel<<<256, 256>>>(Wt_w, Wt_b, Q_w, Q_b, out);
}

// round 9
// speedup vs baseline: 1.0292x; 1.0292x over previous
#include <cuda_runtime.h>
#include <math.h>

#ifndef M_PI
#define M_PI 3.14159265358979323846
#endif

#define NBT 48
#define NC  64
#define NX  128
#define NY  128
#define NB  4
#define TIN 12
#define TOUT 4
#define UD  3
#define NDEPTH 4

typedef unsigned long long u64;

__device__ __forceinline__ u64 f2fma(u64 a, u64 b, u64 c) {
    u64 r; asm("fma.rn.f32x2 %0,%1,%2,%3;" : "=l"(r) : "l"(a), "l"(b), "l"(c)); return r;
}
__device__ __forceinline__ u64 f2sub(u64 a, u64 b) {
    u64 r; asm("sub.rn.f32x2 %0,%1,%2;" : "=l"(r) : "l"(a), "l"(b)); return r;
}
__device__ __forceinline__ u64 f2pack(float lo, float hi) {
    u64 r; asm("mov.b64 %0,{%1,%2};" : "=l"(r) : "f"(lo), "f"(hi)); return r;
}
__device__ __forceinline__ u64 f2dup(float v) { return f2pack(v, v); }
__device__ __forceinline__ float2 f2unpack(u64 a) {
    float2 r; asm("mov.b64 {%0,%1},%2;" : "=f"(r.x), "=f"(r.y) : "l"(a)); return r;
}
__device__ __forceinline__ u64 f2neg(u64 a) { return a ^ 0x8000000080000000ULL; }

// ---------------- scratch ---------------------------------------------------
__device__ float g_X [NBT*NC*NX*NY];
__device__ float g_Yf[NBT*NC*NX*32];
__device__ float g_Zr[NBT*NC*512];
__device__ float g_Zi[NBT*NC*512];
__device__ float g_Or[NBT*NC*512];
__device__ float g_Oi[NBT*NC*512];
__device__ float g_Xi[NBT*NC*NX*32];
__device__ float g_Wfy2[64*32*2];
__device__ float g_Wfx[128*32*2];
__device__ float g_Wix[32*128*2];
__device__ float g_Cy [16*128];
__device__ float g_Sy [16*128];

// ---------------- table init ------------------------------------------------
__global__ void init_tables_kernel() {
    int tid = blockIdx.x * blockDim.x + threadIdx.x;
    if (tid < 64*32) {
        int yp = tid >> 5, k = tid & 31;
        int kk = k & 15;
        for (int j = 0; j < 2; j++) {
            int y = 2*yp + j;
            double th = (2.0 * M_PI / 128.0) * (double)((kk * y) & 127);
            g_Wfy2[tid*2 + j] = (k < 16) ? (float)cos(th) : (float)(-sin(th));
        }
    }
    if (tid < 128*32) {
        int x = tid >> 5, m = tid & 31;
        int kx = (m < 16) ? m : (96 + m);
        double th = (2.0 * M_PI / 128.0) * (double)((kx * x) & 127);
        g_Wfx[2*tid]   = (float)cos(th);
        g_Wfx[2*tid+1] = (float)(-sin(th));
    }
    if (tid < 32*128) {
        int m = tid >> 7, x = tid & 127;
        int kx = (m < 16) ? m : (96 + m);
        double th = (2.0 * M_PI / 128.0) * (double)((kx * x) & 127);
        g_Wix[2*tid]   = (float)(cos(th) / 128.0);
        g_Wix[2*tid+1] = (float)(sin(th) / 128.0);
    }
    if (tid < 16*128) {
        int k = tid >> 7, y = tid & 127;
        if (k == 0) { g_Cy[tid] = 1.0f/128.0f; g_Sy[tid] = 0.0f; }
        else {
            double th = (2.0 * M_PI / 128.0) * (double)((k * y) & 127);
            g_Cy[tid] = (float)( 2.0 * cos(th) / 128.0);
            g_Sy[tid] = (float)(-2.0 * sin(th) / 128.0);
        }
    }
}

// ---------------- fused lift (3->64) + forward y-DFT -----------------------
// grid (128 x, 48 bt), 256 threads
__global__ __launch_bounds__(256) void lift_fwdy_kernel(
    const float* __restrict__ in, const float* __restrict__ Pw,
    const float* __restrict__ Pb)
{
    __shared__ float sL[8192];
    __shared__ float sPw[192], sPb[64], sIn[384];
    int tid = threadIdx.x;
    int x = blockIdx.x, bt = blockIdx.y;

    if (tid < 192) sPw[tid] = Pw[tid];
    if (tid < 64)  sPb[tid] = Pb[tid];
    if (tid < 128) {
#pragma unroll
        for (int u = 0; u < 3; u++)
            sIn[u*128 + tid] = in[((size_t)bt*3 + u)*16384 + x*128 + tid];
    }
    __syncthreads();

    for (int i = tid; i < 8192; i += 256) {
        int c = i >> 7, y = i & 127;
        float v = sPb[c] + sPw[c*3]*sIn[y] + sPw[c*3+1]*sIn[128+y] + sPw[c*3+2]*sIn[256+y];
        sL[i] = v;
        g_X[(((size_t)bt*64 + c)*128 + x)*128 + y] = v;
    }
    __syncthreads();

    int warp = tid >> 5, lane = tid & 31;
    const u64* w2 = (const u64*)g_Wfy2;
    int ob = warp * 8;
    u64 acc[8];
#pragma unroll
    for (int r = 0; r < 8; r++) acc[r] = 0ULL;
#pragma unroll 4
    for (int yp = 0; yp < 64; yp++) {
        u64 w = __ldg(w2 + yp*32 + lane);
#pragma unroll
        for (int r = 0; r < 8; r++) {
            u64 v2 = *(const u64*)(sL + (ob + r)*128 + 2*yp);
            acc[r] = f2fma(v2, w, acc[r]);
        }
    }
#pragma unroll
    for (int r = 0; r < 8; r++) {
        float2 p = f2unpack(acc[r]);
        g_Yf[(((size_t)bt*64 + ob + r)*128 + x)*32 + lane] = p.x + p.y;
    }
}

// ---------------- forward DFT over x (R6 version) --------------------------
__global__ __launch_bounds__(128) void fwd_x_kernel() {
    __shared__ float sY0[4096], sY1[4096];
    int tid = threadIdx.x;
    const float* src = g_Yf + (size_t)blockIdx.x * 8192;
    for (int i = tid; i < 4096; i += 128) { sY0[i] = src[i]; sY1[i] = src[4096 + i]; }
    __syncthreads();
    int m   = tid >> 2;
    int ky0 = (tid & 3) * 4;
    const float2* wtab = (const float2*)g_Wfx;
    u64 rA[2][2], rB[2][2], ii[2][2];
#pragma unroll
    for (int f = 0; f < 2; f++)
#pragma unroll
        for (int p = 0; p < 2; p++) { rA[f][p] = 0ULL; rB[f][p] = 0ULL; ii[f][p] = 0ULL; }
#pragma unroll 2
    for (int x = 0; x < 128; x++) {
        float2 w = __ldg(wtab + x*32 + m);
        u64 wr2 = f2dup(w.x), wi2 = f2dup(w.y);
        u64 a00 = *(const u64*)(sY0 + x*32 + ky0);
        u64 b00 = *(const u64*)(sY0 + x*32 + 16 + ky0);
        u64 a01 = *(const u64*)(sY0 + x*32 + ky0 + 2);
        u64 b01 = *(const u64*)(sY0 + x*32 + 18 + ky0);
        u64 a10 = *(const u64*)(sY1 + x*32 + ky0);
        u64 b10 = *(const u64*)(sY1 + x*32 + 16 + ky0);
        u64 a11 = *(const u64*)(sY1 + x*32 + ky0 + 2);
        u64 b11 = *(const u64*)(sY1 + x*32 + 18 + ky0);
        rA[0][0] = f2fma(a00, wr2, rA[0][0]);  rB[0][0] = f2fma(b00, wi2, rB[0][0]);
        ii[0][0] = f2fma(a00, wi2, ii[0][0]);  ii[0][0] = f2fma(b00, wr2, ii[0][0]);
        rA[0][1] = f2fma(a01, wr2, rA[0][1]);  rB[0][1] = f2fma(b01, wi2, rB[0][1]);
        ii[0][1] = f2fma(a01, wi2, ii[0][1]);  ii[0][1] = f2fma(b01, wr2, ii[0][1]);
        rA[1][0] = f2fma(a10, wr2, rA[1][0]);  rB[1][0] = f2fma(b10, wi2, rB[1][0]);
        ii[1][0] = f2fma(a10, wi2, ii[1][0]);  ii[1][0] = f2fma(b10, wr2, ii[1][0]);
        rA[1][1] = f2fma(a11, wr2, rA[1][1]);  rB[1][1] = f2fma(b11, wi2, rB[1][1]);
        ii[1][1] = f2fma(a11, wi2, ii[1][1]);  ii[1][1] = f2fma(b11, wr2, ii[1][1]);
    }
#pragma unroll
    for (int f = 0; f < 2; f++) {
        size_t base = ((size_t)(blockIdx.x*2 + f))*512 + m*16 + ky0;
        *(u64*)(g_Zr + base)     = f2sub(rA[f][0], rB[f][0]);
        *(u64*)(g_Zr + base + 2) = f2sub(rA[f][1], rB[f][1]);
        *(u64*)(g_Zi + base)     = ii[f][0];
        *(u64*)(g_Zi + base + 2) = ii[f][1];
    }
}

// ---------------- per-mode channel mix (v1: coalesced, high-occ) -----------
__global__ __launch_bounds__(128) void mode_mix_kernel(
    const float* __restrict__ w1r, const float* __restrict__ w1i,
    const float* __restrict__ w2r, const float* __restrict__ w2i)
{
    int mp    = blockIdx.x * 128 + threadIdx.x;
    int mode0 = mp * 2;
    int half  = mode0 >> 8;
    int ml    = mode0 & 255;
    const float* Wr = half ? w2r : w1r;
    const float* Wi = half ? w2i : w1i;
    int bt0 = blockIdx.y * 4, o0 = blockIdx.z * 4;
    u64 aR[4][4], aI[4][4];
#pragma unroll
    for (int b = 0; b < 4; b++)
#pragma unroll
        for (int o = 0; o < 4; o++) { aR[b][o] = 0ULL; aI[b][o] = 0ULL; }

    for (int i = 0; i < 64; i++) {
        u64 zr[4], zi[4];
#pragma unroll
        for (int b = 0; b < 4; b++) {
            size_t zb = ((size_t)(bt0 + b)*64 + i)*512 + mode0;
            zr[b] = *(const u64*)(g_Zr + zb);
            zi[b] = *(const u64*)(g_Zi + zb);
        }
#pragma unroll
        for (int o = 0; o < 4; o++) {
            size_t wb = ((size_t)i*64 + (o0 + o))*256 + ml;
            u64 wr2  = *(const u64*)(Wr + wb);
            u64 wi2  = *(const u64*)(Wi + wb);
            u64 wi2n = f2neg(wi2);
#pragma unroll
            for (int b = 0; b < 4; b++) {
                aR[b][o] = f2fma(zr[b], wr2,  aR[b][o]);
                aR[b][o] = f2fma(zi[b], wi2n, aR[b][o]);
                aI[b][o] = f2fma(zr[b], wi2,  aI[b][o]);
                aI[b][o] = f2fma(zi[b], wr2,  aI[b][o]);
            }
        }
    }
#pragma unroll
    for (int b = 0; b < 4; b++)
#pragma unroll
        for (int o = 0; o < 4; o++) {
            size_t ob = ((size_t)(bt0 + b)*64 + (o0 + o))*512 + mode0;
            *(u64*)(g_Or + ob) = aR[b][o];
            *(u64*)(g_Oi + ob) = aI[b][o];
        }
}

// ---------------- inverse DFT over x ---------------------------------------
__global__ __launch_bounds__(256) void inv_x_kernel() {
    __shared__ float sOr[512], sOi[512];
    int tid = threadIdx.x;
    const float* srcr = g_Or + (size_t)blockIdx.x * 512;
    const float* srci = g_Oi + (size_t)blockIdx.x * 512;
    for (int i = tid; i < 512; i += 256) { sOr[i] = srcr[i]; sOi[i] = srci[i]; }
    __syncthreads();
    int x  = tid >> 1;
    int kb = (tid & 1) * 8;
    u64 arA[4], arB[4], ai[4];
#pragma unroll
    for (int j = 0; j < 4; j++) { arA[j] = 0ULL; arB[j] = 0ULL; ai[j] = 0ULL; }
#pragma unroll 4
    for (int m = 0; m < 32; m++) {
        float2 w = *(const float2*)(g_Wix + (m*128 + x)*2);
        u64 wr2 = f2dup(w.x), wi2 = f2dup(w.y);
#pragma unroll
        for (int j = 0; j < 4; j++) {
            u64 pr = *(const u64*)(sOr + m*16 + kb + 2*j);
            u64 pi = *(const u64*)(sOi + m*16 + kb + 2*j);
            arA[j] = f2fma(pr, wr2, arA[j]);
            arB[j] = f2fma(pi, wi2, arB[j]);
            ai[j]  = f2fma(pr, wi2, ai[j]);
            ai[j]  = f2fma(pi, wr2, ai[j]);
        }
    }
    float* dst = g_Xi + ((size_t)blockIdx.x * 128 + x) * 32;
#pragma unroll
    for (int j = 0; j < 4; j++) {
        *(u64*)(dst + kb + 2*j)      = f2sub(arA[j], arB[j]);
        *(u64*)(dst + 16 + kb + 2*j) = ai[j];
    }
}

// ---------------- fused tail (R7, unchanged) -------------------------------
__global__ __launch_bounds__(256) void fused_tail_kernel(
    const float* __restrict__ gctxd,
    const float* __restrict__ llw,
    const float* __restrict__ llb,
    const float* __restrict__ lng, const float* __restrict__ lnb,
    int write_yf)
{
    extern __shared__ float sm[];
    float* sXV  = sm;
    u64*   sLLd = (u64*)(sm + 8192);
    float* sCtx = sm + 8192;
    u64*   sXid = (u64*)(sm + 16384);
    float* sCy  = sm + 20480;
    float* sSy  = sm + 22528;
    float* sPS  = sm + 24576;
    float* sPQ  = sm + 24832;
    float* sMu  = sm + 25088;
    float* sRs  = sm + 25216;
    float* sLNg = sm + 25344;
    float* sLNb = sm + 25408;
    float* sLLb = sm + 25472;

    int tid = threadIdx.x;
    int x   = blockIdx.x;
    int bt  = blockIdx.y;

    float cxf = x * 0.5f - 0.25f;
    int ix0 = (int)floorf(cxf);
    float wx1 = cxf - (float)ix0, wx0 = 1.0f - wx1;
    int cx0 = min(63, max(0, ix0));
    int cx1 = min(63, max(0, ix0 + 1));

    for (int i = tid; i < 8192; i += 256) {
        int c = i >> 7, y = i & 127;
        sXV[i] = g_X[(((size_t)bt*64 + c)*128 + x)*128 + y];
    }
    for (int i = tid; i < 4096; i += 256) sLLd[i] = f2dup(llw[i]);
    for (int i = tid; i < 2048; i += 256) {
        int o = i >> 5, k = i & 31;
        sXid[i] = f2dup(g_Xi[(((size_t)bt*64 + o)*128 + x)*32 + k]);
    }
    for (int i = tid; i < 2048; i += 256) { sCy[i] = g_Cy[i]; sSy[i] = g_Sy[i]; }
    if (tid < 64) { sLNg[tid] = lng[tid]; sLNb[tid] = lnb[tid]; sLLb[tid] = llb[tid]; }
    __syncthreads();

    int o0  = (tid >> 5) * 8;
    int tx4 = (tid & 31) * 4;
    u64 acc0[8], acc1[8];
#pragma unroll
    for (int oo = 0; oo < 8; oo++) { acc0[oo] = 0ULL; acc1[oo] = 0ULL; }

#pragma unroll 2
    for (int c = 0; c < 64; c++) {
        ulonglong2 xv = *(const ulonglong2*)(sXV + c*128 + tx4);
#pragma unroll
        for (int oo = 0; oo < 8; oo++) {
            u64 w2 = sLLd[(o0 + oo)*64 + c];
            acc0[oo] = f2fma(xv.x, w2, acc0[oo]);
            acc1[oo] = f2fma(xv.y, w2, acc1[oo]);
        }
    }
#pragma unroll
    for (int ky = 0; ky < 16; ky++) {
        ulonglong2 cy = *(const ulonglong2*)(sCy + ky*128 + tx4);
        ulonglong2 sy = *(const ulonglong2*)(sSy + ky*128 + tx4);
#pragma unroll
        for (int oo = 0; oo < 8; oo++) {
            u64 xr2 = sXid[(o0 + oo)*32 + ky];
            u64 xi2 = sXid[(o0 + oo)*32 + 16 + ky];
            acc0[oo] = f2fma(xr2, cy.x, acc0[oo]);
            acc0[oo] = f2fma(xi2, sy.x, acc0[oo]);
            acc1[oo] = f2fma(xr2, cy.y, acc1[oo]);
            acc1[oo] = f2fma(xi2, sy.y, acc1[oo]);
        }
    }
    __syncthreads();
#pragma unroll
    for (int oo = 0; oo < 8; oo++) {
        float b = sLLb[o0 + oo];
        float2 v0 = f2unpack(acc0[oo]);
        float2 v1 = f2unpack(acc1[oo]);
        *(float4*)(sXV + (o0 + oo)*128 + tx4) =
            make_float4(v0.x + b, v0.y + b, v1.x + b, v1.y + b);
    }
    for (int i = tid; i < 8192; i += 256) {
        int o = i >> 7, rest = i & 127;
        int j = rest >> 6, c = rest & 63;
        int cx = j ? cx1 : cx0;
        sCtx[i] = gctxd[((size_t)bt*64 + o)*4096 + cx*64 + c];
    }
    __syncthreads();

    {
        int yy = tid & 127, oh = tid >> 7;
        float s = 0.f, ss = 0.f;
        int ob = oh * 32;
        for (int o = ob; o < ob + 32; o++) {
            float v = sXV[o*128 + yy];
            s += v; ss += v*v;
        }
        sPS[tid] = s; sPQ[tid] = ss;
    }
    __syncthreads();
    if (tid < 128) {
        float s = sPS[tid] + sPS[128 + tid];
        float q = sPQ[tid] + sPQ[128 + tid];
        float mu = s * (1.0f/64.0f);
        float var = q * (1.0f/64.0f) - mu*mu;
        sMu[tid] = mu;
        sRs[tid] = rsqrtf(var + 1e-5f);
    }
    __syncthreads();

    int y = tid & 127;
    float cyf = y * 0.5f - 0.25f;
    int iy0 = (int)floorf(cyf);
    float wy1 = cyf - (float)iy0, wy0 = 1.0f - wy1;
    int cy0 = min(63, max(0, iy0));
    int cy1 = min(63, max(0, iy0 + 1));
    float mu = sMu[y], rs = sRs[y];

    for (int j = 0; j < 32; j++) {
        int idx = j * 256 + tid;
        int o = idx >> 7;
        float v = sXV[o*128 + y];
        v = (v - mu) * rs * sLNg[o] + sLNb[o];
        v = 0.5f * v * (1.0f + erff(v * 0.70710678118654752440f));
        const float* cr = sCtx + o*128;
        float g = wx0 * (wy0 * cr[cy0] + wy1 * cr[cy1])
                + wx1 * (wy0 * cr[64 + cy0] + wy1 * cr[64 + cy1]);
        float fin = v + g;
        g_X[(((size_t)bt*64 + o)*128 + x)*128 + y] = fin;
        sXV[o*128 + y] = fin;
    }

    if (write_yf) {
        __syncthreads();
        int warp = tid >> 5, lane = tid & 31;
        const u64* w2 = (const u64*)g_Wfy2;
        int ob = warp * 8;
        u64 acc[8];
#pragma unroll
        for (int r = 0; r < 8; r++) acc[r] = 0ULL;
#pragma unroll 4
        for (int yp = 0; yp < 64; yp++) {
            u64 w = __ldg(w2 + yp*32 + lane);
#pragma unroll
            for (int r = 0; r < 8; r++) {
                u64 v2 = *(const u64*)(sXV + (ob + r)*128 + 2*yp);
                acc[r] = f2fma(v2, w, acc[r]);
            }
        }
#pragma unroll
        for (int r = 0; r < 8; r++) {
            float2 p = f2unpack(acc[r]);
            g_Yf[(((size_t)bt*64 + ob + r)*128 + x)*32 + lane] = p.x + p.y;
        }
    }
}

// ---------------- temporal aggregation + projection ------------------------
__global__ __launch_bounds__(256) void head_kernel(
    const float* __restrict__ Wtw, const float* __restrict__ Wtb,
    const float* __restrict__ Qw,  const float* __restrict__ Qb,
    float* __restrict__ out)
{
    __shared__ float sWt[48], sWtb[4], sQ[192], sQb[3], sQS[3];
    int tid = threadIdx.x;
    if (tid < 48)  sWt[tid]  = Wtw[tid];
    if (tid < 4)   sWtb[tid] = Wtb[tid];
    if (tid < 192) sQ[tid]   = Qw[tid];
    if (tid < 3)   sQb[tid]  = Qb[tid];
    __syncthreads();
    if (tid < 3) {
        float s = 0.f;
        for (int c = 0; c < 64; c++) s += sQ[tid*64 + c];
        sQS[tid] = s;
    }
    __syncthreads();
    int idx = blockIdx.x * 256 + tid;
    int b = idx >> 14, xy = idx & 16383;
    float acc[TOUT][UD] = {};
    for (int c = 0; c < 64; c++) {
        float xv[TIN];
#pragma unroll
        for (int t = 0; t < TIN; t++)
            xv[t] = g_X[(((size_t)(b*TIN + t))*64 + c)*16384 + xy];
        float tt[TOUT];
#pragma unroll
        for (int o = 0; o < TOUT; o++) {
            float s = 0.f;
#pragma unroll
            for (int t = 0; t < TIN; t++) s += sWt[o*TIN + t] * xv[t];
            tt[o] = s;
        }
#pragma unroll
        for (int u = 0; u < UD; u++) {
            float q = sQ[u*64 + c];
#pragma unroll
            for (int o = 0; o < TOUT; o++) acc[o][u] += q * tt[o];
        }
    }
#pragma unroll
    for (int o = 0; o < TOUT; o++)
#pragma unroll
        for (int u = 0; u < UD; u++)
            out[(((size_t)b*TOUT + o)*UD + u)*16384 + xy] =
                acc[o][u] + sWtb[o]*sQS[u] + sQb[u];
}

// ---------------- launcher --------------------------------------------------
extern "C" void kernel_launch(void* const* d_in, const int* in_sizes, int n_in,
                              void* d_out, int out_size)
{
    const float* input = (const float*)d_in[0];
    const float* gctx  = (const float*)d_in[1];
    const float* P_w   = (const float*)d_in[2];
    const float* P_b   = (const float*)d_in[3];
    const float* Q_w   = (const float*)d_in[4];
    const float* Q_b   = (const float*)d_in[5];
    const float* Wt_w  = (const float*)d_in[6];
    const float* Wt_b  = (const float*)d_in[7];
    const float* w1r   = (const float*)d_in[8];
    const float* w1i   = (const float*)d_in[9];
    const float* w2r   = (const float*)d_in[10];
    const float* w2i   = (const float*)d_in[11];
    const float* ll_w  = (const float*)d_in[12];
    const float* ll_b  = (const float*)d_in[13];
    const float* ln_g  = (const float*)d_in[14];
    const float* ln_b  = (const float*)d_in[15];
    float* out = (float*)d_out;

    const int FUSED_SMEM = 25536 * 4;   // 102144 bytes
    cudaFuncSetAttribute(fused_tail_kernel,
                         cudaFuncAttributeMaxDynamicSharedMemorySize, FUSED_SMEM);

    init_tables_kernel<<<16, 256>>>();
    dim3 gl(128, NBT);
    lift_fwdy_kernel<<<gl, 256>>>(input, P_w, P_b);

    const size_t SPEC_D = (size_t)64*64*16*16;
    for (int d = 0; d < NDEPTH; d++) {
        fwd_x_kernel<<<1536, 128>>>();
        dim3 g3(2, 12, 16);
        mode_mix_kernel<<<g3, 128>>>(w1r + d*SPEC_D, w1i + d*SPEC_D,
                                     w2r + d*SPEC_D, w2i + d*SPEC_D);
        inv_x_kernel<<<NBT*NC, 256>>>();
        dim3 g5(128, NBT);
        fused_tail_kernel<<<g5, 256, FUSED_SMEM>>>(
            gctx + (size_t)d*NBT*64*4096,
            ll_w + (size_t)d*4096, ll_b + d*64, ln_g + d*64, ln_b + d*64,
            (d < NDEPTH-1) ? 1 : 0);
    }
    head_kernel<<<256, 256>>>(Wt_w, Wt_b, Q_w, Q_b, out);
}